// round 16
// baseline (speedup 1.0000x reference)
#include <cuda_runtime.h>
#include <cuda_fp16.h>
#include <cstdint>

// Problem dims
#define SS 512
#define BB 64
#define II 1024
#define HH 1024
#define GG 3072  // 3*H

#define GRP 2        // independent batch groups (both served by every CTA)
#define RPG 32       // batch rows per group
#define NCTA 64      // CTAs; each owns 16 units for BOTH groups
#define H2 512       // half2 words per h row
#define NBUF 8       // h ring depth

// ---------------- global scratch ----------------
__device__ float g_gi[(size_t)SS * BB * GG];        // input projections (fp32)
__device__ unsigned g_h2[GRP][NBUF][RPG * H2];      // h rings, half2, pair-interleaved
__device__ unsigned g_cnt[GRP * 8 * 32];            // per-leaf monotonic counters
__device__ unsigned g_ileaf[4 * 32];                // init barrier (4 leaves x 16)
__device__ unsigned g_iroot;
__device__ unsigned g_igen;

// ---------------- helpers ----------------
__device__ __forceinline__ unsigned packh2(float lo, float hi) {
  __half2 h = __floats2half2_rn(lo, hi);
  return *(unsigned*)&h;
}

// phase-1 permutation (within 8-half2 k16 block)
__device__ __forceinline__ int hperm(int jh) {
  return (jh & ~7) + ((jh & 3) * 2) + ((jh >> 2) & 1);
}

// recurrent h layout: 16-half2 superblock per k16-block PAIR
__device__ __forceinline__ int pairpos(int kk, int jh) {
  const int off = (kk & 1) * 2;
  return (kk >> 1) * 16 + ((jh & 3) * 4) + off + (jh >> 2);
}

__device__ __forceinline__ unsigned ld_acq(const unsigned* p) {
  unsigned v;
  asm volatile("ld.global.acquire.gpu.b32 %0, [%1];" : "=r"(v) : "l"(p));
  return v;
}
__device__ __forceinline__ void red_release_add(unsigned* p, unsigned v) {
  asm volatile("red.release.gpu.global.add.u32 [%0], %1;" :: "l"(p), "r"(v) : "memory");
}

__device__ __forceinline__ float sigmoid_fast(float x) {
  float e;
  asm("ex2.approx.f32 %0, %1;" : "=f"(e) : "f"(-x * 1.4426950408889634f));
  float r;
  asm("rcp.approx.f32 %0, %1;" : "=f"(r) : "f"(1.f + e));
  return r;
}
__device__ __forceinline__ float tanh_fast(float x) {
  float y;
  asm("tanh.approx.f32 %0, %1;" : "=f"(y) : "f"(x));
  return y;
}

__device__ __forceinline__ void mma16(float* c,
                                      unsigned a0, unsigned a1, unsigned a2, unsigned a3,
                                      unsigned b0, unsigned b1) {
  asm volatile(
      "mma.sync.aligned.m16n8k16.row.col.f32.f16.f16.f32 "
      "{%0,%1,%2,%3},{%4,%5,%6,%7},{%8,%9},{%0,%1,%2,%3};"
      : "+f"(c[0]), "+f"(c[1]), "+f"(c[2]), "+f"(c[3])
      : "r"(a0), "r"(a1), "r"(a2), "r"(a3), "r"(b0), "r"(b1));
}

__device__ __forceinline__ uint4 ldg_cg4(const unsigned* p) {
  uint4 v;
  asm volatile("ld.global.cg.v4.u32 {%0,%1,%2,%3}, [%4];"
               : "=r"(v.x), "=r"(v.y), "=r"(v.z), "=r"(v.w) : "l"(p));
  return v;
}

// single-use streams: evict-first policy
__device__ __forceinline__ float ldg_cs(const float* p) {
  float v;
  asm volatile("ld.global.cs.f32 %0, [%1];" : "=f"(v) : "l"(p));
  return v;
}
__device__ __forceinline__ void stg_cs(float* p, float v) {
  asm volatile("st.global.cs.f32 [%0], %1;" :: "l"(p), "f"(v));
}

// =================== Phase 1: gi = x @ W_ih^T + b_ih (fp16 MMA) ===========
#define BM 128
#define BN 128
#define BKK 16
#define AP2 10

__global__ __launch_bounds__(256, 2) void gemm_gi_kernel(
    const float* __restrict__ x, const float* __restrict__ Wih,
    const float* __restrict__ bih) {
  __shared__ unsigned sA[BM * AP2];
  __shared__ unsigned sB[BN * AP2];
  const int tid = threadIdx.x;
  const int m0 = blockIdx.y * BM;
  const int n0 = blockIdx.x * BN;
  const int w = tid >> 5, lane = tid & 31;
  const int gq = lane >> 2, t = lane & 3;
  const int wm = (w & 3) * 32;
  const int wn = (w >> 2) * 64;

  const int lr = tid >> 2;
  const int lc = (tid & 3) * 4;
  const int p0 = hperm(lc >> 1);

  float acc[2][8][4];
#pragma unroll
  for (int mt = 0; mt < 2; mt++)
#pragma unroll
    for (int nt = 0; nt < 8; nt++)
#pragma unroll
      for (int i = 0; i < 4; i++) acc[mt][nt][i] = 0.f;

  float4 pA[2], pB[2];
#pragma unroll
  for (int it = 0; it < 2; it++) {
    pA[it] = *(const float4*)(x + (size_t)(m0 + lr + it * 64) * II + lc);
    pB[it] = *(const float4*)(Wih + (size_t)(n0 + lr + it * 64) * II + lc);
  }
#pragma unroll
  for (int it = 0; it < 2; it++) {
    unsigned* dA = &sA[(lr + it * 64) * AP2];
    dA[p0] = packh2(pA[it].x, pA[it].y);
    dA[p0 + 2] = packh2(pA[it].z, pA[it].w);
    unsigned* dB = &sB[(lr + it * 64) * AP2];
    dB[p0] = packh2(pB[it].x, pB[it].y);
    dB[p0 + 2] = packh2(pB[it].z, pB[it].w);
  }
  __syncthreads();

  for (int k0 = 0; k0 < II; k0 += BKK) {
    const bool more = (k0 + BKK) < II;
    if (more) {
#pragma unroll
      for (int it = 0; it < 2; it++) {
        pA[it] = *(const float4*)(x + (size_t)(m0 + lr + it * 64) * II + k0 + BKK + lc);
        pB[it] = *(const float4*)(Wih + (size_t)(n0 + lr + it * 64) * II + k0 + BKK + lc);
      }
    }
    {
      uint2 a[2][2];
#pragma unroll
      for (int mt = 0; mt < 2; mt++) {
        const unsigned* ap = &sA[(wm + mt * 16 + gq) * AP2 + 2 * t];
        a[mt][0] = *(const uint2*)ap;
        a[mt][1] = *(const uint2*)(ap + 8 * AP2);
      }
#pragma unroll
      for (int nt = 0; nt < 8; nt++) {
        const uint2 b = *(const uint2*)&sB[(wn + nt * 8 + gq) * AP2 + 2 * t];
#pragma unroll
        for (int mt = 0; mt < 2; mt++)
          mma16(acc[mt][nt], a[mt][0].x, a[mt][1].x, a[mt][0].y, a[mt][1].y, b.x, b.y);
      }
    }
    __syncthreads();
    if (more) {
#pragma unroll
      for (int it = 0; it < 2; it++) {
        unsigned* dA = &sA[(lr + it * 64) * AP2];
        dA[p0] = packh2(pA[it].x, pA[it].y);
        dA[p0 + 2] = packh2(pA[it].z, pA[it].w);
        unsigned* dB = &sB[(lr + it * 64) * AP2];
        dB[p0] = packh2(pB[it].x, pB[it].y);
        dB[p0 + 2] = packh2(pB[it].z, pB[it].w);
      }
    }
    __syncthreads();
  }

#pragma unroll
  for (int mt = 0; mt < 2; mt++) {
#pragma unroll
    for (int nt = 0; nt < 8; nt++) {
      const int row = m0 + wm + mt * 16 + gq;
      const int col = n0 + wn + nt * 8 + 2 * t;
      const float b0v = bih[col], b1v = bih[col + 1];
      float* o = g_gi + (size_t)row * GG + col;
      o[0] = acc[mt][nt][0] + b0v;
      o[1] = acc[mt][nt][1] + b1v;
      o = g_gi + (size_t)(row + 8) * GG + col;
      o[0] = acc[mt][nt][2] + b0v;
      o[1] = acc[mt][nt][3] + b1v;
    }
  }
}

// =================== Phase 2: persistent recurrent kernel =================
// 64 CTAs; each CTA owns 16 units for BOTH independent batch groups and
// alternates g0-step / g1-step so each group's publish->poll round trip is
// hidden behind the other group's compute. Per-group structure (leaf sync,
// layouts, counters) is identical to the round-11 optimum.
#define UPC 16
#define NC 48              // 3 gates * 16 units
#define WP2 520            // half2 per W smem row

__global__ __launch_bounds__(256, 1) void gru_rec_kernel(
    const float* __restrict__ Whh, const float* __restrict__ bhh,
    const float* __restrict__ h0, float* __restrict__ out) {
  extern __shared__ unsigned sm[];
  unsigned* sW = sm;                                   // [NC][WP2] half2 (shared by groups)
  float* sGh = (float*)(sW + NC * WP2);                // [GRP][4 kq][RPG][NC]
  float* sBias = sGh + GRP * 4 * RPG * NC;             // [NC]
  float* sHp = sBias + NC;                             // [GRP][512] fp32 own h

  const int tid = threadIdx.x;
  const int cid = blockIdx.x;            // 0..63
  const int u0 = cid * UPC;
  const int myleaf = cid >> 3;

  // ---- init: counters (both groups), W (shared), bias, h0 (both groups) ----
  if (tid == 0 && (cid & 7) == 0) {
    g_cnt[(0 * 8 + myleaf) * 32] = 0;
    g_cnt[(1 * 8 + myleaf) * 32] = 0;
  }
  for (int i = tid; i < NC * (II / 4); i += 256) {
    const int rowl = i >> 8;
    const int c4 = (i & 255) * 4;
    const int gate = rowl / UPC, ul = rowl % UPC;
    const float4 v = *(const float4*)(Whh + (size_t)(gate * HH + u0 + ul) * HH + c4);
    unsigned* d = &sW[rowl * WP2];
    const int p = hperm(c4 >> 1);
    d[p] = packh2(v.x, v.y);
    d[p + 2] = packh2(v.z, v.w);
  }
  if (tid < NC) {
    const int gate = tid / UPC, ul = tid % UPC;
    sBias[tid] = bhh[gate * HH + u0 + ul];
  }
#pragma unroll
  for (int g = 0; g < GRP; g++) {
#pragma unroll
    for (int it = 0; it < 2; it++) {
      const int idx = tid + it * 256;
      const int r = idx >> 4, j = idx & 15;
      const float v = h0[(g * RPG + r) * HH + u0 + j];
      sHp[g * 512 + idx] = v;
      if ((j & 1) == 0) {
        const float v1 = h0[(g * RPG + r) * HH + u0 + j + 1];
        g_h2[g][0][r * H2 + pairpos(cid, j >> 1)] = packh2(v, v1);
      }
    }
  }
  // init barrier (64 CTAs: 4 leaves x 16, root of 4; relaunch-safe)
  {
    __syncthreads();
    if (tid == 0) {
      __threadfence();
      volatile unsigned* genp = &g_igen;
      const unsigned old = *genp;
      const int ileaf = cid >> 4;
      if (atomicAdd(&g_ileaf[ileaf * 32], 1u) == 15u) {
        if (atomicAdd(&g_iroot, 1u) == 3u) {
          g_iroot = 0;
#pragma unroll
          for (int i = 0; i < 4; i++) g_ileaf[i * 32] = 0;
          __threadfence();
          atomicExch((unsigned*)genp, old + 1u);
        }
      }
      while (*genp == old) {}
      __threadfence();
    }
    __syncthreads();
  }

  const int w = tid >> 5, lane = tid & 31;
  const int gq = lane >> 2, t = lane & 3;
  const int mt = (w & 1);   // M tile
  const int kq = (w >> 1);  // K quarter (leaves 2kq, 2kq+1)

  const int r0i = tid >> 4, j0i = tid & 15;
  const int r1i = (tid + 256) >> 4, j1i = tid & 15;

  // gi prefetch for step 0, both groups (evict-first)
  float gir[GRP][2], giz[GRP][2], gin[GRP][2];
#pragma unroll
  for (int g = 0; g < GRP; g++) {
    const float* p0 = g_gi + (size_t)(g * RPG + r0i) * GG + u0 + j0i;
    gir[g][0] = ldg_cs(p0); giz[g][0] = ldg_cs(p0 + HH); gin[g][0] = ldg_cs(p0 + 2 * HH);
    const float* p1 = g_gi + (size_t)(g * RPG + r1i) * GG + u0 + j1i;
    gir[g][1] = ldg_cs(p1); giz[g][1] = ldg_cs(p1 + HH); gin[g][1] = ldg_cs(p1 + 2 * HH);
  }

  for (int s = 0; s < SS; s++) {
    const unsigned fwd_target = 8u * (unsigned)s;

#pragma unroll
    for (int g = 0; g < GRP; g++) {
      const unsigned* cur = g_h2[g][s & (NBUF - 1)];
      unsigned* nxt = g_h2[g][(s + 1) & (NBUF - 1)];
      const int b0 = g * RPG;
      float* sGhg = sGh + g * 4 * RPG * NC;
      float* sHpg = sHp + g * 512;

      // anti-dep poll (NBUF-2 slack; threads 8..15, this group's leaves)
      if (s >= NBUF - 1 && tid >= 8 && tid < 16) {
        const unsigned tgt = 8u * (unsigned)(s - (NBUF - 2));
        const unsigned* cp = &g_cnt[(g * 8 + (tid - 8)) * 32];
        while (ld_acq(cp) < tgt) {}
      }
      // forward poll: the 2 leaves this warp reads
      if (lane < 2) {
        const unsigned* cp = &g_cnt[(g * 8 + 2 * kq + lane) * 32];
        while (ld_acq(cp) < fwd_target) {}
      }
      __syncwarp();

      // burst-load A fragments (L2 path)
      uint4 aLo[8], aHi[8];
      {
        const unsigned* base = cur + (size_t)(mt * 16 + gq) * H2 + kq * 8 * 16 + 4 * t;
#pragma unroll
        for (int p = 0; p < 8; p++) {
          aLo[p] = ldg_cg4(base + p * 16);
          aHi[p] = ldg_cg4(base + 8 * H2 + p * 16);
        }
      }

      float acc[6][4];
#pragma unroll
      for (int nt = 0; nt < 6; nt++)
#pragma unroll
        for (int i = 0; i < 4; i++) acc[nt][i] = 0.f;

#pragma unroll
      for (int p = 0; p < 8; p++) {
        const int kg0 = (kq * 8 + p) * 16 + 2 * t;
#pragma unroll
        for (int nt = 0; nt < 6; nt++) {
          const uint2 b = *(const uint2*)&sW[(nt * 8 + gq) * WP2 + kg0];
          mma16(acc[nt], aLo[p].x, aHi[p].x, aLo[p].y, aHi[p].y, b.x, b.y);
        }
#pragma unroll
        for (int nt = 0; nt < 6; nt++) {
          const uint2 b = *(const uint2*)&sW[(nt * 8 + gq) * WP2 + kg0 + 8];
          mma16(acc[nt], aLo[p].z, aHi[p].z, aLo[p].w, aHi[p].w, b.x, b.y);
        }
      }

      // K-quarter partials
#pragma unroll
      for (int nt = 0; nt < 6; nt++) {
        const int col = nt * 8 + 2 * t;
        float* dst = &sGhg[(kq * RPG + mt * 16 + gq) * NC + col];
        dst[0] = acc[nt][0];
        dst[1] = acc[nt][1];
        dst = &sGhg[(kq * RPG + mt * 16 + 8 + gq) * NC + col];
        dst[0] = acc[nt][2];
        dst[1] = acc[nt][3];
      }
      __syncthreads();

      // pointwise GRU cell (approx MUFU math); STG.64 h write via double shfl
      float hout[2];
#pragma unroll
      for (int it = 0; it < 2; it++) {
        const int idx = tid + it * 256;
        const int r = idx >> 4, j = idx & 15;
        float hr = sBias[j], hz = sBias[UPC + j], hn = sBias[2 * UPC + j];
#pragma unroll
        for (int q = 0; q < 4; q++) {
          const float* pr = &sGhg[(q * RPG + r) * NC];
          hr += pr[j];
          hz += pr[UPC + j];
          hn += pr[2 * UPC + j];
        }
        const float hp = sHpg[idx];
        const float rr = sigmoid_fast(gir[g][it] + hr);
        const float zz = sigmoid_fast(giz[g][it] + hz);
        const float nn = tanh_fast(gin[g][it] + rr * hn);
        const float hnew = nn + zz * (hp - nn);
        sHpg[idx] = hnew;
        hout[it] = hnew;
        const float hi = __shfl_down_sync(0xffffffffu, hnew, 1);
        const unsigned v = packh2(hnew, hi);
        const unsigned vx = __shfl_xor_sync(0xffffffffu, v, 8);
        if ((j & 9) == 0) {
          const int jh = j >> 1;
          unsigned* dst = &nxt[r * H2 + (cid >> 1) * 16 + jh * 4 + (cid & 1) * 2];
          *(uint2*)dst = make_uint2(v, vx);
        }
      }

      // ---- arrive (= publish this group's h_{s+1}) ----
      __syncthreads();
      if (tid == 0)
        red_release_add(&g_cnt[(g * 8 + myleaf) * 32], 1u);

      // slack work for this group: out-stores (evict-first) + next gi prefetch.
      // This slack + the other group's compute block covers the publish->poll RT.
      stg_cs(&out[((size_t)s * BB + b0 + r0i) * HH + u0 + j0i], hout[0]);
      stg_cs(&out[((size_t)s * BB + b0 + r1i) * HH + u0 + j1i], hout[1]);
      if (s == SS - 1) {
        stg_cs(&out[(size_t)SS * BB * HH + (size_t)(b0 + r0i) * HH + u0 + j0i], hout[0]);
        stg_cs(&out[(size_t)SS * BB * HH + (size_t)(b0 + r1i) * HH + u0 + j1i], hout[1]);
      }
      {
        const int sn = (s + 1 < SS) ? s + 1 : s;
        const float* gb = g_gi + (size_t)sn * BB * GG;
        const float* p0 = gb + (size_t)(b0 + r0i) * GG + u0 + j0i;
        gir[g][0] = ldg_cs(p0); giz[g][0] = ldg_cs(p0 + HH); gin[g][0] = ldg_cs(p0 + 2 * HH);
        const float* p1 = gb + (size_t)(b0 + r1i) * GG + u0 + j1i;
        gir[g][1] = ldg_cs(p1); giz[g][1] = ldg_cs(p1 + HH); gin[g][1] = ldg_cs(p1 + 2 * HH);
      }
    }
  }
}

// =================== launch =================
extern "C" void kernel_launch(void* const* d_in, const int* in_sizes, int n_in,
                              void* d_out, int out_size) {
  const float* x   = (const float*)d_in[0];
  const float* h0  = (const float*)d_in[1];
  const float* wih = (const float*)d_in[2];
  const float* whh = (const float*)d_in[3];
  const float* bih = (const float*)d_in[4];
  const float* bhh = (const float*)d_in[5];
  float* out = (float*)d_out;

  const int smem_rec =
      (NC * WP2 + GRP * 4 * RPG * NC + NC + GRP * 512) * 4;  // ~153.4 KB
  cudaFuncSetAttribute(gru_rec_kernel, cudaFuncAttributeMaxDynamicSharedMemorySize, smem_rec);

  gemm_gi_kernel<<<dim3(GG / BN, (SS * BB) / BM), 256>>>(x, wih, bih);
  gru_rec_kernel<<<NCTA, 256, smem_rec>>>(whh, bhh, h0, out);
}

// round 17
// speedup vs baseline: 1.5325x; 1.5325x over previous
#include <cuda_runtime.h>
#include <cuda_fp16.h>
#include <cstdint>

// Problem dims
#define SS 512
#define BB 64
#define II 1024
#define HH 1024
#define GG 3072  // 3*H

#define GRP 2        // independent batch groups
#define RPG 32       // batch rows per group
#define CPG 64       // CTAs per group
#define H2 512       // half2 words per h row
#define NBUF 8       // h ring depth

// ---------------- global scratch ----------------
__device__ float g_gi[(size_t)SS * BB * GG];        // input projections (fp32)
__device__ unsigned g_h2[GRP][NBUF][RPG * H2];      // h ring, half2, pair-interleaved
__device__ unsigned g_cnt[GRP * 8 * 32];            // per-leaf monotonic counters
__device__ unsigned g_ileaf[8 * 32];                // init barrier
__device__ unsigned g_iroot;
__device__ unsigned g_igen;

// ---------------- helpers ----------------
__device__ __forceinline__ unsigned packh2(float lo, float hi) {
  __half2 h = __floats2half2_rn(lo, hi);
  return *(unsigned*)&h;
}

// phase-1 permutation (within 8-half2 k16 block)
__device__ __forceinline__ int hperm(int jh) {
  return (jh & ~7) + ((jh & 3) * 2) + ((jh >> 2) & 1);
}

// recurrent h layout: 16-half2 superblock per k16-block PAIR
__device__ __forceinline__ int pairpos(int kk, int jh) {
  const int off = (kk & 1) * 2;
  return (kk >> 1) * 16 + ((jh & 3) * 4) + off + (jh >> 2);
}

__device__ __forceinline__ unsigned ld_acq(const unsigned* p) {
  unsigned v;
  asm volatile("ld.global.acquire.gpu.b32 %0, [%1];" : "=r"(v) : "l"(p));
  return v;
}
__device__ __forceinline__ void red_release_add(unsigned* p, unsigned v) {
  asm volatile("red.release.gpu.global.add.u32 [%0], %1;" :: "l"(p), "r"(v) : "memory");
}

__device__ __forceinline__ float sigmoid_fast(float x) {
  float e;
  asm("ex2.approx.f32 %0, %1;" : "=f"(e) : "f"(-x * 1.4426950408889634f));
  float r;
  asm("rcp.approx.f32 %0, %1;" : "=f"(r) : "f"(1.f + e));
  return r;
}
__device__ __forceinline__ float tanh_fast(float x) {
  float y;
  asm("tanh.approx.f32 %0, %1;" : "=f"(y) : "f"(x));
  return y;
}

__device__ __forceinline__ void mma16(float* c,
                                      unsigned a0, unsigned a1, unsigned a2, unsigned a3,
                                      unsigned b0, unsigned b1) {
  asm volatile(
      "mma.sync.aligned.m16n8k16.row.col.f32.f16.f16.f32 "
      "{%0,%1,%2,%3},{%4,%5,%6,%7},{%8,%9},{%0,%1,%2,%3};"
      : "+f"(c[0]), "+f"(c[1]), "+f"(c[2]), "+f"(c[3])
      : "r"(a0), "r"(a1), "r"(a2), "r"(a3), "r"(b0), "r"(b1));
}

__device__ __forceinline__ uint4 ldg_cg4(const unsigned* p) {
  uint4 v;
  asm volatile("ld.global.cg.v4.u32 {%0,%1,%2,%3}, [%4];"
               : "=r"(v.x), "=r"(v.y), "=r"(v.z), "=r"(v.w) : "l"(p));
  return v;
}

// single-use streams: evict-first policy
__device__ __forceinline__ float ldg_cs(const float* p) {
  float v;
  asm volatile("ld.global.cs.f32 %0, [%1];" : "=f"(v) : "l"(p));
  return v;
}
__device__ __forceinline__ void stg_cs(float* p, float v) {
  asm volatile("st.global.cs.f32 [%0], %1;" :: "l"(p), "f"(v));
}

// =================== Phase 1: gi = x @ W_ih^T + b_ih (fp16 MMA) ===========
#define BM 128
#define BN 128
#define BKK 16
#define AP2 10

__global__ __launch_bounds__(256, 2) void gemm_gi_kernel(
    const float* __restrict__ x, const float* __restrict__ Wih,
    const float* __restrict__ bih) {
  __shared__ unsigned sA[BM * AP2];
  __shared__ unsigned sB[BN * AP2];
  const int tid = threadIdx.x;
  const int m0 = blockIdx.y * BM;
  const int n0 = blockIdx.x * BN;
  const int w = tid >> 5, lane = tid & 31;
  const int gq = lane >> 2, t = lane & 3;
  const int wm = (w & 3) * 32;
  const int wn = (w >> 2) * 64;

  const int lr = tid >> 2;
  const int lc = (tid & 3) * 4;
  const int p0 = hperm(lc >> 1);

  float acc[2][8][4];
#pragma unroll
  for (int mt = 0; mt < 2; mt++)
#pragma unroll
    for (int nt = 0; nt < 8; nt++)
#pragma unroll
      for (int i = 0; i < 4; i++) acc[mt][nt][i] = 0.f;

  float4 pA[2], pB[2];
#pragma unroll
  for (int it = 0; it < 2; it++) {
    pA[it] = *(const float4*)(x + (size_t)(m0 + lr + it * 64) * II + lc);
    pB[it] = *(const float4*)(Wih + (size_t)(n0 + lr + it * 64) * II + lc);
  }
#pragma unroll
  for (int it = 0; it < 2; it++) {
    unsigned* dA = &sA[(lr + it * 64) * AP2];
    dA[p0] = packh2(pA[it].x, pA[it].y);
    dA[p0 + 2] = packh2(pA[it].z, pA[it].w);
    unsigned* dB = &sB[(lr + it * 64) * AP2];
    dB[p0] = packh2(pB[it].x, pB[it].y);
    dB[p0 + 2] = packh2(pB[it].z, pB[it].w);
  }
  __syncthreads();

  for (int k0 = 0; k0 < II; k0 += BKK) {
    const bool more = (k0 + BKK) < II;
    if (more) {
#pragma unroll
      for (int it = 0; it < 2; it++) {
        pA[it] = *(const float4*)(x + (size_t)(m0 + lr + it * 64) * II + k0 + BKK + lc);
        pB[it] = *(const float4*)(Wih + (size_t)(n0 + lr + it * 64) * II + k0 + BKK + lc);
      }
    }
    {
      uint2 a[2][2];
#pragma unroll
      for (int mt = 0; mt < 2; mt++) {
        const unsigned* ap = &sA[(wm + mt * 16 + gq) * AP2 + 2 * t];
        a[mt][0] = *(const uint2*)ap;
        a[mt][1] = *(const uint2*)(ap + 8 * AP2);
      }
#pragma unroll
      for (int nt = 0; nt < 8; nt++) {
        const uint2 b = *(const uint2*)&sB[(wn + nt * 8 + gq) * AP2 + 2 * t];
#pragma unroll
        for (int mt = 0; mt < 2; mt++)
          mma16(acc[mt][nt], a[mt][0].x, a[mt][1].x, a[mt][0].y, a[mt][1].y, b.x, b.y);
      }
    }
    __syncthreads();
    if (more) {
#pragma unroll
      for (int it = 0; it < 2; it++) {
        unsigned* dA = &sA[(lr + it * 64) * AP2];
        dA[p0] = packh2(pA[it].x, pA[it].y);
        dA[p0 + 2] = packh2(pA[it].z, pA[it].w);
        unsigned* dB = &sB[(lr + it * 64) * AP2];
        dB[p0] = packh2(pB[it].x, pB[it].y);
        dB[p0 + 2] = packh2(pB[it].z, pB[it].w);
      }
    }
    __syncthreads();
  }

#pragma unroll
  for (int mt = 0; mt < 2; mt++) {
#pragma unroll
    for (int nt = 0; nt < 8; nt++) {
      const int row = m0 + wm + mt * 16 + gq;
      const int col = n0 + wn + nt * 8 + 2 * t;
      const float b0v = bih[col], b1v = bih[col + 1];
      float* o = g_gi + (size_t)row * GG + col;
      o[0] = acc[mt][nt][0] + b0v;
      o[1] = acc[mt][nt][1] + b1v;
      o = g_gi + (size_t)(row + 8) * GG + col;
      o[0] = acc[mt][nt][2] + b0v;
      o[1] = acc[mt][nt][3] + b1v;
    }
  }
}

// =================== Phase 2: persistent recurrent kernel =================
// Best-measured design (r11/r15): 2 groups x 64 CTAs, 16 units/CTA;
// leaf-granular arrive-only sync (8 monotonic counters/group); h read
// directly from L2 into MMA fragments; approx MUFU pointwise; out/gi with
// evict-first policy.
#define UPC 16
#define NC 48              // 3 gates * 16 units
#define WP2 520            // half2 per W smem row

__global__ __launch_bounds__(256, 1) void gru_rec_kernel(
    const float* __restrict__ Whh, const float* __restrict__ bhh,
    const float* __restrict__ h0, float* __restrict__ out) {
  extern __shared__ unsigned sm[];
  unsigned* sW = sm;                                   // [NC][WP2] half2 (k16-perm)
  float* sGh = (float*)(sW + NC * WP2);                // [4 kq][RPG][NC]
  float* sBias = sGh + 4 * RPG * NC;                   // [NC]
  float* sHp = sBias + NC;                             // [RPG*UPC] fp32 own h

  const int tid = threadIdx.x;
  const int grp = blockIdx.x >> 6;
  const int cid = blockIdx.x & 63;
  const int u0 = cid * UPC;
  const int b0 = grp * RPG;
  const int myleaf = cid >> 3;

  // ---- init ----
  if (tid == 0 && (cid & 7) == 0) g_cnt[(grp * 8 + myleaf) * 32] = 0;
  for (int i = tid; i < NC * (II / 4); i += 256) {
    const int rowl = i >> 8;
    const int c4 = (i & 255) * 4;
    const int gate = rowl / UPC, ul = rowl % UPC;
    const float4 v = *(const float4*)(Whh + (size_t)(gate * HH + u0 + ul) * HH + c4);
    unsigned* d = &sW[rowl * WP2];
    const int p = hperm(c4 >> 1);
    d[p] = packh2(v.x, v.y);
    d[p + 2] = packh2(v.z, v.w);
  }
  if (tid < NC) {
    const int gate = tid / UPC, ul = tid % UPC;
    sBias[tid] = bhh[gate * HH + u0 + ul];
  }
#pragma unroll
  for (int it = 0; it < 2; it++) {
    const int idx = tid + it * 256;
    const int r = idx >> 4, j = idx & 15;
    const float v = h0[(b0 + r) * HH + u0 + j];
    sHp[idx] = v;
    if ((j & 1) == 0) {
      const float v1 = h0[(b0 + r) * HH + u0 + j + 1];
      g_h2[grp][0][r * H2 + pairpos(cid, j >> 1)] = packh2(v, v1);
    }
  }
  // init barrier (full grid, tree; relaunch-safe)
  {
    __syncthreads();
    if (tid == 0) {
      __threadfence();
      volatile unsigned* genp = &g_igen;
      const unsigned old = *genp;
      const int ileaf = blockIdx.x >> 4;
      if (atomicAdd(&g_ileaf[ileaf * 32], 1u) == 15u) {
        if (atomicAdd(&g_iroot, 1u) == 7u) {
          g_iroot = 0;
#pragma unroll
          for (int i = 0; i < 8; i++) g_ileaf[i * 32] = 0;
          __threadfence();
          atomicExch((unsigned*)genp, old + 1u);
        }
      }
      while (*genp == old) {}
      __threadfence();
    }
    __syncthreads();
  }

  const int w = tid >> 5, lane = tid & 31;
  const int gq = lane >> 2, t = lane & 3;
  const int mt = (w & 1);   // M tile
  const int kq = (w >> 1);  // K quarter (leaves 2kq, 2kq+1)

  const int r0i = tid >> 4, j0i = tid & 15;
  const int r1i = (tid + 256) >> 4, j1i = tid & 15;

  // gi prefetch for step 0 (evict-first: each gi element is read exactly once)
  float gir[2], giz[2], gin[2];
  {
    const float* p0 = g_gi + (size_t)(b0 + r0i) * GG + u0 + j0i;
    gir[0] = ldg_cs(p0); giz[0] = ldg_cs(p0 + HH); gin[0] = ldg_cs(p0 + 2 * HH);
    const float* p1 = g_gi + (size_t)(b0 + r1i) * GG + u0 + j1i;
    gir[1] = ldg_cs(p1); giz[1] = ldg_cs(p1 + HH); gin[1] = ldg_cs(p1 + 2 * HH);
  }

  for (int s = 0; s < SS; s++) {
    const unsigned* cur = g_h2[grp][s & (NBUF - 1)];
    unsigned* nxt = g_h2[grp][(s + 1) & (NBUF - 1)];
    const unsigned fwd_target = 8u * (unsigned)s;

    // anti-dep poll (NBUF-2 slack; threads 8..15)
    if (s >= NBUF - 1 && tid >= 8 && tid < 16) {
      const unsigned tgt = 8u * (unsigned)(s - (NBUF - 2));
      const unsigned* cp = &g_cnt[(grp * 8 + (tid - 8)) * 32];
      while (ld_acq(cp) < tgt) {}
    }
    // forward poll: the 2 leaves this warp reads
    if (lane < 2) {
      const unsigned* cp = &g_cnt[(grp * 8 + 2 * kq + lane) * 32];
      while (ld_acq(cp) < fwd_target) {}
    }
    __syncwarp();

    // burst-load A fragments (L2 path)
    uint4 aLo[8], aHi[8];
    {
      const unsigned* base = cur + (size_t)(mt * 16 + gq) * H2 + kq * 8 * 16 + 4 * t;
#pragma unroll
      for (int p = 0; p < 8; p++) {
        aLo[p] = ldg_cg4(base + p * 16);
        aHi[p] = ldg_cg4(base + 8 * H2 + p * 16);
      }
    }

    float acc[6][4];
#pragma unroll
    for (int nt = 0; nt < 6; nt++)
#pragma unroll
      for (int i = 0; i < 4; i++) acc[nt][i] = 0.f;

#pragma unroll
    for (int p = 0; p < 8; p++) {
      const int kg0 = (kq * 8 + p) * 16 + 2 * t;
#pragma unroll
      for (int nt = 0; nt < 6; nt++) {
        const uint2 b = *(const uint2*)&sW[(nt * 8 + gq) * WP2 + kg0];
        mma16(acc[nt], aLo[p].x, aHi[p].x, aLo[p].y, aHi[p].y, b.x, b.y);
      }
#pragma unroll
      for (int nt = 0; nt < 6; nt++) {
        const uint2 b = *(const uint2*)&sW[(nt * 8 + gq) * WP2 + kg0 + 8];
        mma16(acc[nt], aLo[p].z, aHi[p].z, aLo[p].w, aHi[p].w, b.x, b.y);
      }
    }

    // K-quarter partials
#pragma unroll
    for (int nt = 0; nt < 6; nt++) {
      const int col = nt * 8 + 2 * t;
      float* dst = &sGh[(kq * RPG + mt * 16 + gq) * NC + col];
      dst[0] = acc[nt][0];
      dst[1] = acc[nt][1];
      dst = &sGh[(kq * RPG + mt * 16 + 8 + gq) * NC + col];
      dst[0] = acc[nt][2];
      dst[1] = acc[nt][3];
    }
    __syncthreads();

    // pointwise GRU cell (approx MUFU math); STG.64 h write via double shfl
    float hout[2];
#pragma unroll
    for (int it = 0; it < 2; it++) {
      const int idx = tid + it * 256;
      const int r = idx >> 4, j = idx & 15;
      float hr = sBias[j], hz = sBias[UPC + j], hn = sBias[2 * UPC + j];
#pragma unroll
      for (int q = 0; q < 4; q++) {
        const float* pr = &sGh[(q * RPG + r) * NC];
        hr += pr[j];
        hz += pr[UPC + j];
        hn += pr[2 * UPC + j];
      }
      const float hp = sHp[idx];
      const float rr = sigmoid_fast(gir[it] + hr);
      const float zz = sigmoid_fast(giz[it] + hz);
      const float nn = tanh_fast(gin[it] + rr * hn);
      const float hnew = nn + zz * (hp - nn);
      sHp[idx] = hnew;
      hout[it] = hnew;
      const float hi = __shfl_down_sync(0xffffffffu, hnew, 1);
      const unsigned v = packh2(hnew, hi);
      const unsigned vx = __shfl_xor_sync(0xffffffffu, v, 8);
      if ((j & 9) == 0) {
        const int jh = j >> 1;
        unsigned* dst = &nxt[r * H2 + (cid >> 1) * 16 + jh * 4 + (cid & 1) * 2];
        *(uint2*)dst = make_uint2(v, vx);
      }
    }

    // ---- arrive (= publish h_{s+1}) via release-reduction ----
    __syncthreads();
    if (tid == 0)
      red_release_add(&g_cnt[(grp * 8 + myleaf) * 32], 1u);

    // slack work: out-stores (evict-first) + next gi prefetch (evict-first)
    stg_cs(&out[((size_t)s * BB + b0 + r0i) * HH + u0 + j0i], hout[0]);
    stg_cs(&out[((size_t)s * BB + b0 + r1i) * HH + u0 + j1i], hout[1]);
    if (s == SS - 1) {
      stg_cs(&out[(size_t)SS * BB * HH + (size_t)(b0 + r0i) * HH + u0 + j0i], hout[0]);
      stg_cs(&out[(size_t)SS * BB * HH + (size_t)(b0 + r1i) * HH + u0 + j1i], hout[1]);
    }
    {
      const int sn = (s + 1 < SS) ? s + 1 : s;
      const float* gb = g_gi + (size_t)sn * BB * GG;
      const float* p0 = gb + (size_t)(b0 + r0i) * GG + u0 + j0i;
      gir[0] = ldg_cs(p0); giz[0] = ldg_cs(p0 + HH); gin[0] = ldg_cs(p0 + 2 * HH);
      const float* p1 = gb + (size_t)(b0 + r1i) * GG + u0 + j1i;
      gir[1] = ldg_cs(p1); giz[1] = ldg_cs(p1 + HH); gin[1] = ldg_cs(p1 + 2 * HH);
    }
  }
}

// =================== launch =================
extern "C" void kernel_launch(void* const* d_in, const int* in_sizes, int n_in,
                              void* d_out, int out_size) {
  const float* x   = (const float*)d_in[0];
  const float* h0  = (const float*)d_in[1];
  const float* wih = (const float*)d_in[2];
  const float* whh = (const float*)d_in[3];
  const float* bih = (const float*)d_in[4];
  const float* bhh = (const float*)d_in[5];
  float* out = (float*)d_out;

  const int smem_rec = (NC * WP2 + 4 * RPG * NC + NC + RPG * UPC) * 4;  // ~126.6 KB
  cudaFuncSetAttribute(gru_rec_kernel, cudaFuncAttributeMaxDynamicSharedMemorySize, smem_rec);

  gemm_gi_kernel<<<dim3(GG / BN, (SS * BB) / BM), 256>>>(x, wih, bih);
  gru_rec_kernel<<<GRP * CPG, 256, smem_rec>>>(whh, bhh, h0, out);
}